// round 11
// baseline (speedup 1.0000x reference)
#include <cuda_runtime.h>
#include <math.h>

// ---------------- problem constants ----------------
constexpr int kB    = 64;
constexpr int kSVIT = 257;
constexpr int kSQ   = 32;
constexpr int kL    = 512;
constexpr int kIMG  = 1408;
constexpr int kHID  = 768;
constexpr int kC    = 30000;
constexpr int kHC   = 32;   // H_CLUB
constexpr int kHM   = 64;   // H_MINE

constexpr int kIMG4 = kIMG / 4;   // 352 float4 columns
constexpr int kHID4 = kHID / 4;   // 192 float4 columns

// ---------------- scratch (device globals; no allocation) ----------------
__device__ __align__(16) float  g_hist[kB * kC];
__device__ __align__(16) float  g_xv[kB * kIMG];
__device__ __align__(16) float  g_xq[kB * kHID];
__device__ __align__(16) float  g_hmu[kB * kHC];
__device__ __align__(16) float  g_hlv[kB * kHC];
__device__ float  g_T0[kB];
__device__ float  g_T1[kB];
__device__ double g_acc;

__device__ __forceinline__ void f4add(float4& a, const float4 v) {
    a.x += v.x; a.y += v.y; a.z += v.z; a.w += v.w;
}

// ---------------- K1: fused zero+scatter histogram ----------------------
// One block per batch row b: zero the row, sync, scatter its 512 labels.
// Float atomic adds of 1.0 — exact small-int counts, order-independent.
__global__ void __launch_bounds__(256) k_hist(const int* __restrict__ label) {
    int b = blockIdx.x, t = threadIdx.x;
    float4* row4 = reinterpret_cast<float4*>(g_hist + b * kC);
    for (int i = t; i < kC / 4; i += 256)
        row4[i] = make_float4(0.f, 0.f, 0.f, 0.f);
    if (b == 0 && t == 0) g_acc = 0.0;
    __syncthreads();
    #pragma unroll
    for (int r = 0; r < 2; r++) {
        int l = label[b * kL + r * 256 + t];
        if (l == -100) l = 0;
        atomicAdd(&g_hist[b * kC + l], 1.0f);
    }
}

// ---------------- K2: vit mean — 8 s-lanes per column (exact) ------------
__global__ void __launch_bounds__(256) k_vit_mean(const float* __restrict__ vit) {
    int tx = threadIdx.x & 31;    // column within group
    int ty = threadIdx.x >> 5;    // s-lane 0..7
    int b  = blockIdx.y;
    int c  = blockIdx.x * 32 + tx;
    const float4* p = reinterpret_cast<const float4*>(vit) + (size_t)b * kSVIT * kIMG4 + c;
    float4 a = make_float4(0.f, 0.f, 0.f, 0.f);
    for (int s = ty; s < kSVIT; s += 8)
        f4add(a, p[(size_t)s * kIMG4]);
    __shared__ float4 sm[8][32];
    sm[ty][tx] = a;
    __syncthreads();
    if (ty == 0) {
        float4 A0 = sm[0][tx], A1 = sm[1][tx], A2 = sm[2][tx], A3 = sm[3][tx];
        float4 A4 = sm[4][tx], A5 = sm[5][tx], A6 = sm[6][tx], A7 = sm[7][tx];
        float4 r;
        r.x = (((A0.x+A1.x)+(A2.x+A3.x)) + ((A4.x+A5.x)+(A6.x+A7.x))) / (float)kSVIT;
        r.y = (((A0.y+A1.y)+(A2.y+A3.y)) + ((A4.y+A5.y)+(A6.y+A7.y))) / (float)kSVIT;
        r.z = (((A0.z+A1.z)+(A2.z+A3.z)) + ((A4.z+A5.z)+(A6.z+A7.z))) / (float)kSVIT;
        r.w = (((A0.w+A1.w)+(A2.w+A3.w)) + ((A4.w+A5.w)+(A6.w+A7.w))) / (float)kSVIT;
        reinterpret_cast<float4*>(g_xv)[b * kIMG4 + c] = r;
    }
}

// ---------------- K3: qformer mean — 4 s-lanes per column (exact) --------
__global__ void __launch_bounds__(128) k_q_mean(const float* __restrict__ qf) {
    int tx = threadIdx.x & 31;    // column within group
    int ty = threadIdx.x >> 5;    // s-lane 0..3
    int b  = blockIdx.y;
    int c  = blockIdx.x * 32 + tx;
    const float4* p = reinterpret_cast<const float4*>(qf) + (size_t)b * kSQ * kHID4 + c;
    float4 a = make_float4(0.f, 0.f, 0.f, 0.f);
    #pragma unroll
    for (int s = 0; s < kSQ; s += 4)
        f4add(a, p[(size_t)(s + ty) * kHID4]);
    __shared__ float4 sm[4][32];
    sm[ty][tx] = a;
    __syncthreads();
    if (ty == 0) {
        float4 A0 = sm[0][tx], A1 = sm[1][tx], A2 = sm[2][tx], A3 = sm[3][tx];
        float4 r;
        r.x = ((A0.x+A1.x)+(A2.x+A3.x)) / (float)kSQ;
        r.y = ((A0.y+A1.y)+(A2.y+A3.y)) / (float)kSQ;
        r.z = ((A0.z+A1.z)+(A2.z+A3.z)) / (float)kSQ;
        r.w = ((A0.w+A1.w)+(A2.w+A3.w)) / (float)kSQ;
        reinterpret_cast<float4*>(g_xq)[b * kHID4 + c] = r;
    }
}

// ---------------- K4a: CLUB layer-1 head (xq only) -----------------------
// Same lanes / combine tree / values as the fused k_heads CLUB branch.
__global__ void __launch_bounds__(256) k_club(
        const float* __restrict__ Wmu1, const float* __restrict__ bmu1,
        const float* __restrict__ Wlv1, const float* __restrict__ blv1) {
    int b = blockIdx.x, t = threadIdx.x;
    __shared__ float s_club[4][64];   // [lane][head*32+j]
    {
        int lane = t >> 6;            // k-lane 0..3
        int idx  = t & 63;            // head*32 + j
        int j    = idx & 31;
        const float* W  = (idx < 32) ? Wmu1 : Wlv1;
        const float* xq = g_xq + b * kHID;
        float a = 0.f;
        for (int k = lane; k < kHID; k += 4)
            a = fmaf(xq[k], W[k * kHC + j], a);
        s_club[lane][idx] = a;
    }
    __syncthreads();
    if (t < 64) {
        int j = t & 31;
        const float* bb = (t < 32) ? bmu1 : blv1;
        float h = fmaxf(((s_club[0][t] + s_club[1][t]) +
                         (s_club[2][t] + s_club[3][t])) + bb[j], 0.f);
        if (t < 32) g_hmu[b * kHC + j] = h;
        else        g_hlv[b * kHC + j] = h;
    }
}

// ---------------- K4b: MINE head + sequential T dot ----------------------
__global__ void __launch_bounds__(512) k_mine(
        const float* __restrict__ Wt1,  const float* __restrict__ bt1,
        const float* __restrict__ Wt2,  const float* __restrict__ bt2,
        const int*   __restrict__ rand_idx) {
    int b = blockIdx.x, t = threadIdx.x;
    __shared__ float s_mine[4][128];  // [lane][which*64+u]
    __shared__ float s_h0[kHM], s_h1[kHM];
    {
        int lane = t >> 7;            // k-lane 0..3
        int idx  = t & 127;           // which*64 + u
        int u    = idx & 63;
        int qrow = (idx < 64) ? b : rand_idx[b];
        const float* xv = g_xv + (size_t)b    * kIMG;
        const float* xq = g_xq + (size_t)qrow * kHID;
        float a = 0.f;
        for (int k = lane; k < kIMG; k += 4)
            a = fmaf(xv[k], Wt1[k * kHM + u], a);
        for (int k = lane; k < kHID; k += 4)
            a = fmaf(xq[k], Wt1[(kIMG + k) * kHM + u], a);
        s_mine[lane][idx] = a;
    }
    __syncthreads();
    if (t < 128) {
        int u = t & 63;
        float h = fmaxf(((s_mine[0][t] + s_mine[1][t]) +
                         (s_mine[2][t] + s_mine[3][t])) + bt1[u], 0.f);
        if (t < 64) s_h0[u] = h;
        else        s_h1[u] = h;
    }
    __syncthreads();
    if (t == 0) {                     // strict sequential T dot (unchanged)
        float a = 0.f, c2 = 0.f;
        for (int u = 0; u < kHM; u++) {
            float w = Wt2[u];
            a  = fmaf(s_h0[u], w, a);
            c2 = fmaf(s_h1[u], w, c2);
        }
        g_T0[b] = a  + bt2[0];
        g_T1[b] = c2 + bt2[0];
    }
}

// ---------------- K5: I_zy — sparse-aware scan over (b,c) (exact) --------
__global__ void __launch_bounds__(128) k_izy(
        const float* __restrict__ Wmu2, const float* __restrict__ bmu2,
        const float* __restrict__ Wlv2, const float* __restrict__ blv2,
        const int*   __restrict__ perm_idx) {
    __shared__ float s_hmu[kB * kHC];
    __shared__ float s_hlv[kB * kHC];
    __shared__ int   s_perm[kB];
    int tx = threadIdx.x;
    for (int i = tx; i < kB * kHC; i += blockDim.x) {
        s_hmu[i] = g_hmu[i];
        s_hlv[i] = g_hlv[i];
    }
    if (tx < kB) s_perm[tx] = perm_idx[tx];
    __syncthreads();

    int c = blockIdx.x * blockDim.x + tx;
    double acc = 0.0;
    if (c < kC) {
        float wm[kHC], wl[kHC];
        #pragma unroll
        for (int j = 0; j < kHC; j++) {
            wm[j] = Wmu2[j * kC + c];
            wl[j] = Wlv2[j * kC + c];
        }
        float bm = bmu2[c], bl = blv2[c];
        for (int b0 = 0; b0 < kB; b0 += 8) {
            float ys[8], yps[8];
            #pragma unroll
            for (int j = 0; j < 8; j++) {
                ys[j]  = g_hist[(b0 + j) * kC + c];
                yps[j] = g_hist[s_perm[b0 + j] * kC + c];
            }
            #pragma unroll
            for (int q = 0; q < 8; q++) {
                int b = b0 + q;
                float y = ys[q], yp = yps[q];
                if (y != 0.f || yp != 0.f) {
                    y  *= (1.f / kL);
                    yp *= (1.f / kL);
                    float mu = 0.f, lv = 0.f;
                    #pragma unroll
                    for (int j = 0; j < kHC; j++) {
                        mu = fmaf(s_hmu[b * kHC + j], wm[j], mu);
                        lv = fmaf(s_hlv[b * kHC + j], wl[j], lv);
                    }
                    mu += bm;
                    lv = tanhf(lv + bl);
                    float iv = 1.f / (expf(lv) + 1e-6f);
                    float dp = mu - y;
                    float dn = mu - yp;
                    acc += (double)((dn * dn - dp * dp) * iv);
                }
            }
        }
    }

    __shared__ double red[128];
    red[tx] = acc;
    __syncthreads();
    for (int s = 64; s > 0; s >>= 1) {
        if (tx < s) red[tx] += red[tx + s];
        __syncthreads();
    }
    if (tx == 0) atomicAdd(&g_acc, red[0]);
}

// ---------------- K6: finalize — all-parallel latency, strict fp32 tail --
__global__ void k_final(float* __restrict__ out) {
    int t = threadIdx.x;                 // 64 threads
    int lane = t & 31, warp = t >> 5;
    __shared__ float s_e[kB];
    __shared__ float s_t0[kB];
    __shared__ float s_wmax[2];

    float t1 = g_T1[t];
    s_t0[t] = g_T0[t];

    float m = t1;                        // exact warp amax
    #pragma unroll
    for (int off = 16; off > 0; off >>= 1)
        m = fmaxf(m, __shfl_xor_sync(0xffffffffu, m, off));
    if (lane == 0) s_wmax[warp] = m;
    __syncthreads();
    float amax = fmaxf(s_wmax[0], s_wmax[1]);

    s_e[t] = (float)exp((double)(t1 - amax));  // parallel CR fp32 exp
    __syncthreads();

    if (t == 0) {
        float esum = 0.f, t0sum = 0.f;
        for (int b = 0; b < kB; b++) {   // strict sequential fp32 sums
            esum  = esum + s_e[b];
            t0sum = t0sum + s_t0[b];
        }
        float t0m  = t0sum / 64.0f;
        float lgs  = (float)log((double)esum);
        float lse  = lgs + amax;
        float logB = (float)log(64.0);
        float d    = lse - logB;
        float ixz  = t0m - d;
        float izy  = (float)g_acc / 128.0f;
        out[0] = izy - 0.1f * ixz;
    }
}

// ---------------- launch (izy in the ncu capture slot = 4th launch) ------
extern "C" void kernel_launch(void* const* d_in, const int* in_sizes, int n_in,
                              void* d_out, int out_size) {
    const float* vit   = (const float*)d_in[0];
    const float* qf    = (const float*)d_in[1];
    const int*   label = (const int*)  d_in[2];
    const int*   perm  = (const int*)  d_in[3];
    const int*   rnd   = (const int*)  d_in[4];
    const float* Wmu1  = (const float*)d_in[5];
    const float* bmu1  = (const float*)d_in[6];
    const float* Wmu2  = (const float*)d_in[7];
    const float* bmu2  = (const float*)d_in[8];
    const float* Wlv1  = (const float*)d_in[9];
    const float* blv1  = (const float*)d_in[10];
    const float* Wlv2  = (const float*)d_in[11];
    const float* blv2  = (const float*)d_in[12];
    const float* Wt1   = (const float*)d_in[13];
    const float* bt1   = (const float*)d_in[14];
    const float* Wt2   = (const float*)d_in[15];
    const float* bt2   = (const float*)d_in[16];
    float* out = (float*)d_out;

    k_hist<<<kB, 256>>>(label);                          // 1
    k_q_mean<<<dim3(kHID4 / 32, kB), 128>>>(qf);         // 2
    k_club<<<kB, 256>>>(Wmu1, bmu1, Wlv1, blv1);         // 3
    k_izy<<<(kC + 127) / 128, 128>>>(Wmu2, bmu2, Wlv2, blv2, perm);  // 4 ← ncu
    k_vit_mean<<<dim3(kIMG4 / 32, kB), 256>>>(vit);      // 5
    k_mine<<<kB, 512>>>(Wt1, bt1, Wt2, bt2, rnd);        // 6
    k_final<<<1, 64>>>(out);                             // 7
}

// round 12
// speedup vs baseline: 1.3731x; 1.3731x over previous
#include <cuda_runtime.h>
#include <math.h>

// ---------------- problem constants ----------------
constexpr int kB    = 64;
constexpr int kSVIT = 257;
constexpr int kSQ   = 32;
constexpr int kL    = 512;
constexpr int kIMG  = 1408;
constexpr int kHID  = 768;
constexpr int kC    = 30000;
constexpr int kHC   = 32;   // H_CLUB
constexpr int kHM   = 64;   // H_MINE

constexpr int kIMG4 = kIMG / 4;   // 352 float4 columns
constexpr int kHID4 = kHID / 4;   // 192 float4 columns

// izy b-split
constexpr int kYG   = 4;          // b groups
constexpr int kBG   = kB / kYG;   // 16 b per group

// ---------------- scratch (device globals; no allocation) ----------------
__device__ __align__(16) float  g_hist[kB * kC];
__device__ __align__(16) float  g_xv[kB * kIMG];
__device__ __align__(16) float  g_xq[kB * kHID];
__device__ __align__(16) float  g_hmu[kB * kHC];
__device__ __align__(16) float  g_hlv[kB * kHC];
__device__ float  g_T0[kB];
__device__ float  g_T1[kB];
__device__ double g_acc;

__device__ __forceinline__ void f4add(float4& a, const float4 v) {
    a.x += v.x; a.y += v.y; a.z += v.z; a.w += v.w;
}

// ---------------- K0: zero hist + accumulator ----------------
__global__ void k_zero() {
    int idx = blockIdx.x * blockDim.x + threadIdx.x;
    float4* p = reinterpret_cast<float4*>(g_hist);
    if (idx < (kB * kC) / 4) p[idx] = make_float4(0.f, 0.f, 0.f, 0.f);
    if (idx == 0) g_acc = 0.0;
}

// ---------------- K1: scatter labels into histogram ----------------------
__global__ void k_scatter(const int* __restrict__ label) {
    int i = blockIdx.x * blockDim.x + threadIdx.x;
    if (i < kB * kL) {
        int l = label[i];
        if (l == -100) l = 0;
        int b = i / kL;
        atomicAdd(&g_hist[b * kC + l], 1.0f);
    }
}

// ---------------- K2: vit mean — 8 s-lanes per column (exact) ------------
__global__ void __launch_bounds__(256) k_vit_mean(const float* __restrict__ vit) {
    int tx = threadIdx.x & 31;    // column within group
    int ty = threadIdx.x >> 5;    // s-lane 0..7
    int b  = blockIdx.y;
    int c  = blockIdx.x * 32 + tx;
    const float4* p = reinterpret_cast<const float4*>(vit) + (size_t)b * kSVIT * kIMG4 + c;
    float4 a = make_float4(0.f, 0.f, 0.f, 0.f);
    for (int s = ty; s < kSVIT; s += 8)
        f4add(a, p[(size_t)s * kIMG4]);
    __shared__ float4 sm[8][32];
    sm[ty][tx] = a;
    __syncthreads();
    if (ty == 0) {
        float4 A0 = sm[0][tx], A1 = sm[1][tx], A2 = sm[2][tx], A3 = sm[3][tx];
        float4 A4 = sm[4][tx], A5 = sm[5][tx], A6 = sm[6][tx], A7 = sm[7][tx];
        float4 r;
        r.x = (((A0.x+A1.x)+(A2.x+A3.x)) + ((A4.x+A5.x)+(A6.x+A7.x))) / (float)kSVIT;
        r.y = (((A0.y+A1.y)+(A2.y+A3.y)) + ((A4.y+A5.y)+(A6.y+A7.y))) / (float)kSVIT;
        r.z = (((A0.z+A1.z)+(A2.z+A3.z)) + ((A4.z+A5.z)+(A6.z+A7.z))) / (float)kSVIT;
        r.w = (((A0.w+A1.w)+(A2.w+A3.w)) + ((A4.w+A5.w)+(A6.w+A7.w))) / (float)kSVIT;
        reinterpret_cast<float4*>(g_xv)[b * kIMG4 + c] = r;
    }
}

// ---------------- K3: qformer mean — 4 s-lanes per column (exact) --------
__global__ void __launch_bounds__(128) k_q_mean(const float* __restrict__ qf) {
    int tx = threadIdx.x & 31;    // column within group
    int ty = threadIdx.x >> 5;    // s-lane 0..3
    int b  = blockIdx.y;
    int c  = blockIdx.x * 32 + tx;
    const float4* p = reinterpret_cast<const float4*>(qf) + (size_t)b * kSQ * kHID4 + c;
    float4 a = make_float4(0.f, 0.f, 0.f, 0.f);
    #pragma unroll
    for (int s = 0; s < kSQ; s += 4)
        f4add(a, p[(size_t)(s + ty) * kHID4]);
    __shared__ float4 sm[4][32];
    sm[ty][tx] = a;
    __syncthreads();
    if (ty == 0) {
        float4 A0 = sm[0][tx], A1 = sm[1][tx], A2 = sm[2][tx], A3 = sm[3][tx];
        float4 r;
        r.x = ((A0.x+A1.x)+(A2.x+A3.x)) / (float)kSQ;
        r.y = ((A0.y+A1.y)+(A2.y+A3.y)) / (float)kSQ;
        r.z = ((A0.z+A1.z)+(A2.z+A3.z)) / (float)kSQ;
        r.w = ((A0.w+A1.w)+(A2.w+A3.w)) / (float)kSQ;
        reinterpret_cast<float4*>(g_xq)[b * kHID4 + c] = r;
    }
}

// ---------------- K4: small MLP heads — 4 k-lanes per output (R10 exact) -
__global__ void __launch_bounds__(768) k_heads(
        const float* __restrict__ Wmu1, const float* __restrict__ bmu1,
        const float* __restrict__ Wlv1, const float* __restrict__ blv1,
        const float* __restrict__ Wt1,  const float* __restrict__ bt1,
        const float* __restrict__ Wt2,  const float* __restrict__ bt2,
        const int*   __restrict__ rand_idx) {
    int b = blockIdx.x, t = threadIdx.x;
    __shared__ float s_club[4][64];   // [lane][head*32+j]
    __shared__ float s_mine[4][128];  // [lane][which*64+u]
    __shared__ float s_h0[kHM], s_h1[kHM];

    if (t < 256) {
        int lane = t >> 6;            // k-lane 0..3
        int idx  = t & 63;            // head*32 + j
        int j    = idx & 31;
        const float* W  = (idx < 32) ? Wmu1 : Wlv1;
        const float* xq = g_xq + b * kHID;
        float a = 0.f;
        for (int k = lane; k < kHID; k += 4)
            a = fmaf(xq[k], W[k * kHC + j], a);
        s_club[lane][idx] = a;
    } else {
        int m    = t - 256;
        int lane = m >> 7;            // k-lane 0..3
        int idx  = m & 127;           // which*64 + u
        int u    = idx & 63;
        int qrow = (idx < 64) ? b : rand_idx[b];
        const float* xv = g_xv + (size_t)b    * kIMG;
        const float* xq = g_xq + (size_t)qrow * kHID;
        float a = 0.f;
        for (int k = lane; k < kIMG; k += 4)
            a = fmaf(xv[k], Wt1[k * kHM + u], a);
        for (int k = lane; k < kHID; k += 4)
            a = fmaf(xq[k], Wt1[(kIMG + k) * kHM + u], a);
        s_mine[lane][idx] = a;
    }
    __syncthreads();

    if (t < 64) {
        int j = t & 31;
        const float* bb = (t < 32) ? bmu1 : blv1;
        float h = fmaxf(((s_club[0][t] + s_club[1][t]) +
                         (s_club[2][t] + s_club[3][t])) + bb[j], 0.f);
        if (t < 32) g_hmu[b * kHC + j] = h;
        else        g_hlv[b * kHC + j] = h;
    } else if (t < 192) {
        int idx = t - 64;             // which*64 + u
        int u = idx & 63;
        float h = fmaxf(((s_mine[0][idx] + s_mine[1][idx]) +
                         (s_mine[2][idx] + s_mine[3][idx])) + bt1[u], 0.f);
        if (idx < 64) s_h0[u] = h;
        else          s_h1[u] = h;
    }
    __syncthreads();
    if (t == 0) {                     // strict sequential T dot (unchanged)
        float a = 0.f, c2 = 0.f;
        for (int u = 0; u < kHM; u++) {
            float w = Wt2[u];
            a  = fmaf(s_h0[u], w, a);
            c2 = fmaf(s_h1[u], w, c2);
        }
        g_T0[b] = a  + bt2[0];
        g_T1[b] = c2 + bt2[0];
    }
}

// ---------------- K5: I_zy — low-reg sparse scan, 4-way b-split ----------
// W loads deferred into the (rare) active-pair dot: no 64-reg preload, so
// occupancy is block-limited at 940 blocks (6.4/SM) instead of 235.
// Per-term fp32 math and per-thread b order are unchanged; only the
// grouping of the DOUBLE g_acc atomics changes (sub-ulp at fp32 output).
__global__ void __launch_bounds__(128) k_izy(
        const float* __restrict__ Wmu2, const float* __restrict__ bmu2,
        const float* __restrict__ Wlv2, const float* __restrict__ blv2,
        const int*   __restrict__ perm_idx) {
    __shared__ float s_hmu[kBG * kHC];
    __shared__ float s_hlv[kBG * kHC];
    __shared__ int   s_perm[kBG];
    int tx = threadIdx.x;
    int bbase = blockIdx.y * kBG;
    for (int i = tx; i < kBG * kHC; i += blockDim.x) {
        s_hmu[i] = g_hmu[bbase * kHC + i];
        s_hlv[i] = g_hlv[bbase * kHC + i];
    }
    if (tx < kBG) s_perm[tx] = perm_idx[bbase + tx];
    __syncthreads();

    int c = blockIdx.x * blockDim.x + tx;
    double acc = 0.0;
    if (c < kC) {
        float bm = bmu2[c], bl = blv2[c];
        for (int b0 = 0; b0 < kBG; b0 += 8) {
            float ys[8], yps[8];
            #pragma unroll
            for (int j = 0; j < 8; j++) {
                ys[j]  = g_hist[(bbase + b0 + j) * kC + c];
                yps[j] = g_hist[s_perm[b0 + j] * kC + c];
            }
            #pragma unroll
            for (int q = 0; q < 8; q++) {
                int bl_i = b0 + q;        // local b (ascending within group)
                float y = ys[q], yp = yps[q];
                if (y != 0.f || yp != 0.f) {
                    y  *= (1.f / kL);
                    yp *= (1.f / kL);
                    float mu = 0.f, lv = 0.f;
                    #pragma unroll
                    for (int j = 0; j < kHC; j++) {
                        mu = fmaf(s_hmu[bl_i * kHC + j], Wmu2[j * kC + c], mu);
                        lv = fmaf(s_hlv[bl_i * kHC + j], Wlv2[j * kC + c], lv);
                    }
                    mu += bm;
                    lv = tanhf(lv + bl);
                    float iv = 1.f / (expf(lv) + 1e-6f);
                    float dp = mu - y;
                    float dn = mu - yp;
                    acc += (double)((dn * dn - dp * dp) * iv);
                }
            }
        }
    }

    __shared__ double red[128];
    red[tx] = acc;
    __syncthreads();
    for (int s = 64; s > 0; s >>= 1) {
        if (tx < s) red[tx] += red[tx + s];
        __syncthreads();
    }
    if (tx == 0) atomicAdd(&g_acc, red[0]);
}

// ---------------- K6: finalize — all-parallel latency, strict fp32 tail --
__global__ void k_final(float* __restrict__ out) {
    int t = threadIdx.x;                 // 64 threads
    int lane = t & 31, warp = t >> 5;
    __shared__ float s_e[kB];
    __shared__ float s_t0[kB];
    __shared__ float s_wmax[2];

    float t1 = g_T1[t];
    s_t0[t] = g_T0[t];

    float m = t1;                        // exact warp amax
    #pragma unroll
    for (int off = 16; off > 0; off >>= 1)
        m = fmaxf(m, __shfl_xor_sync(0xffffffffu, m, off));
    if (lane == 0) s_wmax[warp] = m;
    __syncthreads();
    float amax = fmaxf(s_wmax[0], s_wmax[1]);

    s_e[t] = (float)exp((double)(t1 - amax));  // parallel CR fp32 exp
    __syncthreads();

    if (t == 0) {
        float esum = 0.f, t0sum = 0.f;
        for (int b = 0; b < kB; b++) {   // strict sequential fp32 sums
            esum  = esum + s_e[b];
            t0sum = t0sum + s_t0[b];
        }
        float t0m  = t0sum / 64.0f;
        float lgs  = (float)log((double)esum);
        float lse  = lgs + amax;
        float logB = (float)log(64.0);
        float d    = lse - logB;
        float ixz  = t0m - d;
        float izy  = (float)g_acc / 128.0f;
        out[0] = izy - 0.1f * ixz;
    }
}

// ---------------- launch (R10 order; vit in the ncu capture slot) --------
extern "C" void kernel_launch(void* const* d_in, const int* in_sizes, int n_in,
                              void* d_out, int out_size) {
    const float* vit   = (const float*)d_in[0];
    const float* qf    = (const float*)d_in[1];
    const int*   label = (const int*)  d_in[2];
    const int*   perm  = (const int*)  d_in[3];
    const int*   rnd   = (const int*)  d_in[4];
    const float* Wmu1  = (const float*)d_in[5];
    const float* bmu1  = (const float*)d_in[6];
    const float* Wmu2  = (const float*)d_in[7];
    const float* bmu2  = (const float*)d_in[8];
    const float* Wlv1  = (const float*)d_in[9];
    const float* blv1  = (const float*)d_in[10];
    const float* Wlv2  = (const float*)d_in[11];
    const float* blv2  = (const float*)d_in[12];
    const float* Wt1   = (const float*)d_in[13];
    const float* bt1   = (const float*)d_in[14];
    const float* Wt2   = (const float*)d_in[15];
    const float* bt2   = (const float*)d_in[16];
    float* out = (float*)d_out;

    k_zero<<<(kB * kC / 4 + 255) / 256, 256>>>();
    k_scatter<<<(kB * kL + 255) / 256, 256>>>(label);
    k_q_mean<<<dim3(kHID4 / 32, kB), 128>>>(qf);
    k_vit_mean<<<dim3(kIMG4 / 32, kB), 256>>>(vit);   // ncu capture slot
    k_heads<<<kB, 768>>>(Wmu1, bmu1, Wlv1, blv1, Wt1, bt1, Wt2, bt2, rnd);
    k_izy<<<dim3((kC + 127) / 128, kYG), 128>>>(Wmu2, bmu2, Wlv2, blv2, perm);
    k_final<<<1, 64>>>(out);
}

// round 14
// speedup vs baseline: 1.5461x; 1.1259x over previous
#include <cuda_runtime.h>
#include <math.h>

// ---------------- problem constants ----------------
constexpr int kB    = 64;
constexpr int kSVIT = 257;
constexpr int kSQ   = 32;
constexpr int kL    = 512;
constexpr int kIMG  = 1408;
constexpr int kHID  = 768;
constexpr int kC    = 30000;
constexpr int kHC   = 32;   // H_CLUB
constexpr int kHM   = 64;   // H_MINE

constexpr int kIMG4 = kIMG / 4;   // 352 float4 columns
constexpr int kHID4 = kHID / 4;   // 192 float4 columns

// izy b-split
constexpr int kYG   = 4;          // b groups
constexpr int kBG   = kB / kYG;   // 16 b per group

// ---------------- scratch (device globals; no allocation) ----------------
__device__ __align__(16) float  g_hist[kB * kC];
__device__ __align__(16) float  g_xv[kB * kIMG];
__device__ __align__(16) float  g_xq[kB * kHID];
__device__ __align__(16) float  g_hmu[kB * kHC];
__device__ __align__(16) float  g_hlv[kB * kHC];
__device__ float  g_T0[kB];
__device__ float  g_T1[kB];
__device__ double g_acc;

__device__ __forceinline__ void f4add(float4& a, const float4 v) {
    a.x += v.x; a.y += v.y; a.z += v.z; a.w += v.w;
}

// ---------------- K0: zero hist + accumulator ----------------
__global__ void k_zero() {
    int idx = blockIdx.x * blockDim.x + threadIdx.x;
    float4* p = reinterpret_cast<float4*>(g_hist);
    if (idx < (kB * kC) / 4) p[idx] = make_float4(0.f, 0.f, 0.f, 0.f);
    if (idx == 0) g_acc = 0.0;
}

// ---------------- K1: scatter labels into histogram ----------------------
__global__ void k_scatter(const int* __restrict__ label) {
    int i = blockIdx.x * blockDim.x + threadIdx.x;
    if (i < kB * kL) {
        int l = label[i];
        if (l == -100) l = 0;
        int b = i / kL;
        atomicAdd(&g_hist[b * kC + l], 1.0f);
    }
}

// ---------------- K2: vit mean — 8 s-lanes per column (exact) ------------
__global__ void __launch_bounds__(256) k_vit_mean(const float* __restrict__ vit) {
    int tx = threadIdx.x & 31;    // column within group
    int ty = threadIdx.x >> 5;    // s-lane 0..7
    int b  = blockIdx.y;
    int c  = blockIdx.x * 32 + tx;
    const float4* p = reinterpret_cast<const float4*>(vit) + (size_t)b * kSVIT * kIMG4 + c;
    float4 a = make_float4(0.f, 0.f, 0.f, 0.f);
    for (int s = ty; s < kSVIT; s += 8)
        f4add(a, p[(size_t)s * kIMG4]);
    __shared__ float4 sm[8][32];
    sm[ty][tx] = a;
    __syncthreads();
    if (ty == 0) {
        float4 A0 = sm[0][tx], A1 = sm[1][tx], A2 = sm[2][tx], A3 = sm[3][tx];
        float4 A4 = sm[4][tx], A5 = sm[5][tx], A6 = sm[6][tx], A7 = sm[7][tx];
        float4 r;
        r.x = (((A0.x+A1.x)+(A2.x+A3.x)) + ((A4.x+A5.x)+(A6.x+A7.x))) / (float)kSVIT;
        r.y = (((A0.y+A1.y)+(A2.y+A3.y)) + ((A4.y+A5.y)+(A6.y+A7.y))) / (float)kSVIT;
        r.z = (((A0.z+A1.z)+(A2.z+A3.z)) + ((A4.z+A5.z)+(A6.z+A7.z))) / (float)kSVIT;
        r.w = (((A0.w+A1.w)+(A2.w+A3.w)) + ((A4.w+A5.w)+(A6.w+A7.w))) / (float)kSVIT;
        reinterpret_cast<float4*>(g_xv)[b * kIMG4 + c] = r;
    }
}

// ---------------- K3: qformer mean — 4 s-lanes per column (exact) --------
__global__ void __launch_bounds__(128) k_q_mean(const float* __restrict__ qf) {
    int tx = threadIdx.x & 31;    // column within group
    int ty = threadIdx.x >> 5;    // s-lane 0..3
    int b  = blockIdx.y;
    int c  = blockIdx.x * 32 + tx;
    const float4* p = reinterpret_cast<const float4*>(qf) + (size_t)b * kSQ * kHID4 + c;
    float4 a = make_float4(0.f, 0.f, 0.f, 0.f);
    #pragma unroll
    for (int s = 0; s < kSQ; s += 4)
        f4add(a, p[(size_t)(s + ty) * kHID4]);
    __shared__ float4 sm[4][32];
    sm[ty][tx] = a;
    __syncthreads();
    if (ty == 0) {
        float4 A0 = sm[0][tx], A1 = sm[1][tx], A2 = sm[2][tx], A3 = sm[3][tx];
        float4 r;
        r.x = ((A0.x+A1.x)+(A2.x+A3.x)) / (float)kSQ;
        r.y = ((A0.y+A1.y)+(A2.y+A3.y)) / (float)kSQ;
        r.z = ((A0.z+A1.z)+(A2.z+A3.z)) / (float)kSQ;
        r.w = ((A0.w+A1.w)+(A2.w+A3.w)) / (float)kSQ;
        reinterpret_cast<float4*>(g_xq)[b * kHID4 + c] = r;
    }
}

// ---------------- K4a: CLUB layer-1 head (identical values) --------------
__global__ void __launch_bounds__(256) k_club(
        const float* __restrict__ Wmu1, const float* __restrict__ bmu1,
        const float* __restrict__ Wlv1, const float* __restrict__ blv1) {
    int b = blockIdx.x, t = threadIdx.x;
    __shared__ float s_club[4][64];   // [lane][head*32+j]
    {
        int lane = t >> 6;            // k-lane 0..3
        int idx  = t & 63;            // head*32 + j
        int j    = idx & 31;
        const float* W  = (idx < 32) ? Wmu1 : Wlv1;
        const float* xq = g_xq + b * kHID;
        float a = 0.f;
        for (int k = lane; k < kHID; k += 4)
            a = fmaf(xq[k], W[k * kHC + j], a);
        s_club[lane][idx] = a;
    }
    __syncthreads();
    if (t < 64) {
        int j = t & 31;
        const float* bb = (t < 32) ? bmu1 : blv1;
        float h = fmaxf(((s_club[0][t] + s_club[1][t]) +
                         (s_club[2][t] + s_club[3][t])) + bb[j], 0.f);
        if (t < 32) g_hmu[b * kHC + j] = h;
        else        g_hlv[b * kHC + j] = h;
    }
}

// ---------------- K4b: MINE head + strict sequential T dot ---------------
__global__ void __launch_bounds__(512) k_mine(
        const float* __restrict__ Wt1,  const float* __restrict__ bt1,
        const float* __restrict__ Wt2,  const float* __restrict__ bt2,
        const int*   __restrict__ rand_idx) {
    int b = blockIdx.x, t = threadIdx.x;
    __shared__ float s_mine[4][128];  // [lane][which*64+u]
    __shared__ float s_h0[kHM], s_h1[kHM];
    {
        int lane = t >> 7;            // k-lane 0..3
        int idx  = t & 127;           // which*64 + u
        int u    = idx & 63;
        int qrow = (idx < 64) ? b : rand_idx[b];
        const float* xv = g_xv + (size_t)b    * kIMG;
        const float* xq = g_xq + (size_t)qrow * kHID;
        float a = 0.f;
        for (int k = lane; k < kIMG; k += 4)
            a = fmaf(xv[k], Wt1[k * kHM + u], a);
        for (int k = lane; k < kHID; k += 4)
            a = fmaf(xq[k], Wt1[(kIMG + k) * kHM + u], a);
        s_mine[lane][idx] = a;
    }
    __syncthreads();
    if (t < 128) {
        int u = t & 63;
        float h = fmaxf(((s_mine[0][t] + s_mine[1][t]) +
                         (s_mine[2][t] + s_mine[3][t])) + bt1[u], 0.f);
        if (t < 64) s_h0[u] = h;
        else        s_h1[u] = h;
    }
    __syncthreads();
    if (t == 0) {                     // strict sequential T dot (unchanged)
        float a = 0.f, c2 = 0.f;
        for (int u = 0; u < kHM; u++) {
            float w = Wt2[u];
            a  = fmaf(s_h0[u], w, a);
            c2 = fmaf(s_h1[u], w, c2);
        }
        g_T0[b] = a  + bt2[0];
        g_T1[b] = c2 + bt2[0];
    }
}

// ---------------- K5: I_zy — low-reg sparse scan, 4-way b-split ----------
__global__ void __launch_bounds__(128) k_izy(
        const float* __restrict__ Wmu2, const float* __restrict__ bmu2,
        const float* __restrict__ Wlv2, const float* __restrict__ blv2,
        const int*   __restrict__ perm_idx) {
    __shared__ float s_hmu[kBG * kHC];
    __shared__ float s_hlv[kBG * kHC];
    __shared__ int   s_perm[kBG];
    int tx = threadIdx.x;
    int bbase = blockIdx.y * kBG;
    for (int i = tx; i < kBG * kHC; i += blockDim.x) {
        s_hmu[i] = g_hmu[bbase * kHC + i];
        s_hlv[i] = g_hlv[bbase * kHC + i];
    }
    if (tx < kBG) s_perm[tx] = perm_idx[bbase + tx];
    __syncthreads();

    int c = blockIdx.x * blockDim.x + tx;
    double acc = 0.0;
    if (c < kC) {
        float bm = bmu2[c], bl = blv2[c];
        for (int b0 = 0; b0 < kBG; b0 += 8) {
            float ys[8], yps[8];
            #pragma unroll
            for (int j = 0; j < 8; j++) {
                ys[j]  = g_hist[(bbase + b0 + j) * kC + c];
                yps[j] = g_hist[s_perm[b0 + j] * kC + c];
            }
            #pragma unroll
            for (int q = 0; q < 8; q++) {
                int bl_i = b0 + q;        // local b (ascending within group)
                float y = ys[q], yp = yps[q];
                if (y != 0.f || yp != 0.f) {
                    y  *= (1.f / kL);
                    yp *= (1.f / kL);
                    float mu = 0.f, lv = 0.f;
                    #pragma unroll
                    for (int j = 0; j < kHC; j++) {
                        mu = fmaf(s_hmu[bl_i * kHC + j], Wmu2[j * kC + c], mu);
                        lv = fmaf(s_hlv[bl_i * kHC + j], Wlv2[j * kC + c], lv);
                    }
                    mu += bm;
                    lv = tanhf(lv + bl);
                    float iv = 1.f / (expf(lv) + 1e-6f);
                    float dp = mu - y;
                    float dn = mu - yp;
                    acc += (double)((dn * dn - dp * dp) * iv);
                }
            }
        }
    }

    __shared__ double red[128];
    red[tx] = acc;
    __syncthreads();
    for (int s = 64; s > 0; s >>= 1) {
        if (tx < s) red[tx] += red[tx + s];
        __syncthreads();
    }
    if (tx == 0) atomicAdd(&g_acc, red[0]);
}

// ---------------- K6: finalize — all-parallel latency, strict fp32 tail --
__global__ void k_final(float* __restrict__ out) {
    int t = threadIdx.x;                 // 64 threads
    int lane = t & 31, warp = t >> 5;
    __shared__ float s_e[kB];
    __shared__ float s_t0[kB];
    __shared__ float s_wmax[2];

    float t1 = g_T1[t];
    s_t0[t] = g_T0[t];

    float m = t1;                        // exact warp amax
    #pragma unroll
    for (int off = 16; off > 0; off >>= 1)
        m = fmaxf(m, __shfl_xor_sync(0xffffffffu, m, off));
    if (lane == 0) s_wmax[warp] = m;
    __syncthreads();
    float amax = fmaxf(s_wmax[0], s_wmax[1]);

    s_e[t] = (float)exp((double)(t1 - amax));  // parallel CR fp32 exp
    __syncthreads();

    if (t == 0) {
        float esum = 0.f, t0sum = 0.f;
        for (int b = 0; b < kB; b++) {   // strict sequential fp32 sums
            esum  = esum + s_e[b];
            t0sum = t0sum + s_t0[b];
        }
        float t0m  = t0sum / 64.0f;
        float lgs  = (float)log((double)esum);
        float lse  = lgs + amax;
        float logB = (float)log(64.0);
        float d    = lse - logB;
        float ixz  = t0m - d;
        float izy  = (float)g_acc / 128.0f;
        out[0] = izy - 0.1f * ixz;
    }
}

// ---------------- launch: fork/join stream DAG inside the capture --------
extern "C" void kernel_launch(void* const* d_in, const int* in_sizes, int n_in,
                              void* d_out, int out_size) {
    const float* vit   = (const float*)d_in[0];
    const float* qf    = (const float*)d_in[1];
    const int*   label = (const int*)  d_in[2];
    const int*   perm  = (const int*)  d_in[3];
    const int*   rnd   = (const int*)  d_in[4];
    const float* Wmu1  = (const float*)d_in[5];
    const float* bmu1  = (const float*)d_in[6];
    const float* Wmu2  = (const float*)d_in[7];
    const float* bmu2  = (const float*)d_in[8];
    const float* Wlv1  = (const float*)d_in[9];
    const float* blv1  = (const float*)d_in[10];
    const float* Wlv2  = (const float*)d_in[11];
    const float* blv2  = (const float*)d_in[12];
    const float* Wt1   = (const float*)d_in[13];
    const float* bt1   = (const float*)d_in[14];
    const float* Wt2   = (const float*)d_in[15];
    const float* bt2   = (const float*)d_in[16];
    float* out = (float*)d_out;

    // streams/events created once, on the first (non-captured) call
    static cudaStream_t s1 = nullptr, s2 = nullptr;
    static cudaEvent_t evRoot, evQ, evClub, evIzy;
    if (s1 == nullptr) {
        cudaStreamCreateWithFlags(&s1, cudaStreamNonBlocking);
        cudaStreamCreateWithFlags(&s2, cudaStreamNonBlocking);
        cudaEventCreateWithFlags(&evRoot, cudaEventDisableTiming);
        cudaEventCreateWithFlags(&evQ,    cudaEventDisableTiming);
        cudaEventCreateWithFlags(&evClub, cudaEventDisableTiming);
        cudaEventCreateWithFlags(&evIzy,  cudaEventDisableTiming);
    }

    // fork from the capture (default) stream
    cudaEventRecord(evRoot, 0);
    cudaStreamWaitEvent(s1, evRoot, 0);
    cudaStreamWaitEvent(s2, evRoot, 0);

    // main: the 92MB stream
    k_vit_mean<<<dim3(kIMG4 / 32, kB), 256>>>(vit);                  // L1 (0)

    // s2: q -> club
    k_q_mean<<<dim3(kHID4 / 32, kB), 128, 0, s2>>>(qf);              // L2 (s2)
    cudaEventRecord(evQ, s2);
    k_club<<<kB, 256, 0, s2>>>(Wmu1, bmu1, Wlv1, blv1);              // L3 (s2)
    cudaEventRecord(evClub, s2);

    // main: mine after vit (stream order) and q (event)
    cudaStreamWaitEvent(0, evQ, 0);
    k_mine<<<kB, 512>>>(Wt1, bt1, Wt2, bt2, rnd);                    // L4 (0) ← ncu slot

    // s1: hist chain -> izy (after club)
    k_zero<<<(kB * kC / 4 + 255) / 256, 256, 0, s1>>>();             // L5 (s1)
    k_scatter<<<(kB * kL + 255) / 256, 256, 0, s1>>>(label);         // L6 (s1)
    cudaStreamWaitEvent(s1, evClub, 0);
    k_izy<<<dim3((kC + 127) / 128, kYG), 128, 0, s1>>>(Wmu2, bmu2, Wlv2, blv2, perm); // L7 (s1)
    cudaEventRecord(evIzy, s1);

    // join everything back into the capture stream
    cudaStreamWaitEvent(0, evIzy, 0);
    k_final<<<1, 64>>>(out);                                          // L8 (0)
}